// round 2
// baseline (speedup 1.0000x reference)
#include <cuda_runtime.h>
#include <cuda_fp16.h>
#include <math.h>
#include <stdint.h>

// Problem constants
#define BATCH   32
#define CHAN    256
#define HH      56
#define WW      56
#define HWHW    (HH*WW)                 // 3136
#define NX      (BATCH*CHAN*HWHW)       // 25690112
#define NWEIGHT (CHAN*CHAN*9)           // 589824
#define KDIM    2304                    // CHAN*9
#define MDIM    (BATCH*HWHW)            // 100352

// GEMM tiling
#define BM 128
#define BN 256
#define BK 16
#define NKCHUNK 144                     // KDIM/BK
#define NCHUNK  (2*NKCHUNK)             // two passes: x_hi, x_lo

// ---------------- device scratch (static: no allocations allowed) ----------
__device__ __half g_xsplit[2][NX];          // fp16 hi/lo split of x (~103 MB)
__device__ __half g_wmat[KDIM*CHAN];        // quantized weights*15 as [k][oc]
__device__ float  g_scale[CHAN];            // inv/15  (BN scale folded)
__device__ float  g_bias[CHAN];             // beta - mean*inv
__device__ float  g_part[256];
__device__ float  g_T;

__device__ __forceinline__ uint32_t smem_u32(const void* p) {
    return (uint32_t)__cvta_generic_to_shared(p);
}

// ---------------- kernel 1: partial max |tanh(w)| ---------------------------
__global__ void k_reduce1(const float* __restrict__ w) {
    __shared__ float s[256];
    float m = 0.0f;
    for (int i = blockIdx.x*256 + threadIdx.x; i < NWEIGHT; i += 256*256) {
        float t = (float)tanh((double)w[i]);
        m = fmaxf(m, fabsf(t));
    }
    s[threadIdx.x] = m;
    __syncthreads();
    for (int o = 128; o > 0; o >>= 1) {
        if (threadIdx.x < o) s[threadIdx.x] = fmaxf(s[threadIdx.x], s[threadIdx.x+o]);
        __syncthreads();
    }
    if (threadIdx.x == 0) g_part[blockIdx.x] = s[0];
}

__global__ void k_reduce2() {
    __shared__ float s[256];
    s[threadIdx.x] = g_part[threadIdx.x];
    __syncthreads();
    for (int o = 128; o > 0; o >>= 1) {
        if (threadIdx.x < o) s[threadIdx.x] = fmaxf(s[threadIdx.x], s[threadIdx.x+o]);
        __syncthreads();
    }
    if (threadIdx.x == 0) g_T = s[0];
}

// ---------------- kernel 2: quantize weights -> integer m = 15*wq (fp16) ----
// w layout [oc][ci][kh][kw]; flat e = oc*2304 + k where k = ci*9+kh*3+kw.
// Destination: g_wmat[k*256 + oc].
__global__ void k_prep_w(const float* __restrict__ w) {
    int e = blockIdx.x*256 + threadIdx.x;      // grid 2304*256 == NWEIGHT exactly
    float T = g_T;
    float t  = (float)tanh((double)w[e]);
    float tq = __fdiv_rn(t, 2.0f*T) + 0.5f;    // in [0,1]
    float r  = rintf(tq * 15.0f);              // half-even, matches jnp.round
    int oc = e / KDIM;
    int k  = e - oc*KDIM;
    g_wmat[k*CHAN + oc] = __float2half(2.0f*r - 15.0f);   // exact odd integer
}

// ---------------- kernel 3: BN fold ----------------------------------------
__global__ void k_prep_bn(const float* __restrict__ gamma, const float* __restrict__ beta,
                          const float* __restrict__ mean,  const float* __restrict__ var) {
    int oc = threadIdx.x;
    float inv = __fdiv_rn(gamma[oc], __fsqrt_rn(var[oc] + 1e-5f));
    g_scale[oc] = __fdiv_rn(inv, 15.0f);
    g_bias[oc]  = fmaf(-mean[oc], inv, beta[oc]);
}

// ---------------- kernel 4: split x into fp16 hi + lo -----------------------
__global__ void k_convert(const float* __restrict__ x) {
    int i = blockIdx.x*256 + threadIdx.x;      // grid covers NX/4 exactly
    float4 v = reinterpret_cast<const float4*>(x)[i];
    __half h0 = __float2half(v.x), h1 = __float2half(v.y);
    __half h2 = __float2half(v.z), h3 = __float2half(v.w);
    __half l0 = __float2half(v.x - __half2float(h0));
    __half l1 = __float2half(v.y - __half2float(h1));
    __half l2 = __float2half(v.z - __half2float(h2));
    __half l3 = __float2half(v.w - __half2float(h3));
    __half2* hi = reinterpret_cast<__half2*>(&g_xsplit[0][0]);
    __half2* lo = reinterpret_cast<__half2*>(&g_xsplit[1][0]);
    hi[i*2]   = __halves2half2(h0, h1);
    hi[i*2+1] = __halves2half2(h2, h3);
    lo[i*2]   = __halves2half2(l0, l1);
    lo[i*2+1] = __halves2half2(l2, l3);
}

// ---------------- main conv: implicit GEMM with mma.sync fp16 ---------------
__device__ __forceinline__ void fetch_tiles(int c, int b, int hm, int wmm, int ak,
                                            int brow, int bcol,
                                            __half areg[4], uint4& breg) {
    int pass = (c >= NKCHUNK) ? 1 : 0;
    int k0 = (c - pass*NKCHUNK) * BK;
    const __half* xp = g_xsplit[pass];
    int xb = b * CHAN * HWHW;
    #pragma unroll
    for (int j = 0; j < 4; j++) {
        int k  = k0 + ak + j;
        int ci = k / 9;  int r9 = k - ci*9;
        int kh = r9 / 3; int kw = r9 - kh*3;
        int h = hm + kh - 1;
        int w = wmm + kw - 1;
        __half v = __float2half(0.0f);
        if ((unsigned)h < (unsigned)HH && (unsigned)w < (unsigned)WW)
            v = xp[xb + ci*HWHW + h*WW + w];
        areg[j] = v;
    }
    breg = *reinterpret_cast<const uint4*>(&g_wmat[(k0 + brow)*CHAN + bcol]);
}

__global__ __launch_bounds__(512, 1)
void k_conv(const float* __restrict__ alpha_p, float* __restrict__ out) {
    __shared__ __half As[2][BM][BK+8];     // row stride 48B: LDSM conflict-free
    __shared__ __half Bs[2][BK][BN+8];     // row stride 528B (== 16 mod 128): conflict-free
    __shared__ float s_scale[CHAN], s_bias[CHAN];

    int tid  = threadIdx.x;
    int warp = tid >> 5, lane = tid & 31;
    int wm = warp >> 2, wn = warp & 3;     // 4x4 warp grid; warp tile 32(M)x64(N)

    if (tid < CHAN) { s_scale[tid] = g_scale[tid]; s_bias[tid] = g_bias[tid]; }

    int m0 = blockIdx.x * BM;

    // A loader coords: each thread loads 4 consecutive k for one local m row
    int am = tid >> 2;                 // 0..127
    int ak = (tid & 3) * 4;            // 0,4,8,12
    int gm = m0 + am;
    int b  = gm / HWHW; int hw = gm - b*HWHW;
    int hm = hw / WW;   int wmm = hw - hm*WW;

    // B loader coords: 8 contiguous oc per thread (16B vector)
    int brow = tid >> 5;               // 0..15
    int bcol = (lane) * 8;             // 0..248

    float acc[2][8][4];
    #pragma unroll
    for (int mf = 0; mf < 2; mf++)
        #pragma unroll
        for (int nf = 0; nf < 8; nf++)
            #pragma unroll
            for (int j = 0; j < 4; j++) acc[mf][nf][j] = 0.0f;

    __half areg[4]; uint4 breg;
    fetch_tiles(0, b, hm, wmm, ak, brow, bcol, areg, breg);
    #pragma unroll
    for (int j = 0; j < 4; j++) As[0][am][ak+j] = areg[j];
    *reinterpret_cast<uint4*>(&Bs[0][brow][bcol]) = breg;
    __syncthreads();

    for (int c = 0; c < NCHUNK; c++) {
        int buf = c & 1;
        if (c + 1 < NCHUNK)
            fetch_tiles(c+1, b, hm, wmm, ak, brow, bcol, areg, breg);

        // ---- compute on buf ----
        uint32_t afr[2][4];
        uint32_t bfr[8][2];
        #pragma unroll
        for (int mf = 0; mf < 2; mf++) {
            int row = wm*32 + mf*16 + (lane & 15);
            int col = (lane >> 4) << 3;
            uint32_t addr = smem_u32(&As[buf][row][col]);
            asm volatile("ldmatrix.sync.aligned.m8n8.x4.shared.b16 {%0,%1,%2,%3},[%4];"
                : "=r"(afr[mf][0]), "=r"(afr[mf][1]), "=r"(afr[mf][2]), "=r"(afr[mf][3])
                : "r"(addr));
        }
        #pragma unroll
        for (int bg = 0; bg < 4; bg++) {
            int row = lane & 15;
            int col = wn*64 + bg*16 + ((lane >> 4) << 3);
            uint32_t addr = smem_u32(&Bs[buf][row][col]);
            asm volatile("ldmatrix.sync.aligned.m8n8.x4.trans.shared.b16 {%0,%1,%2,%3},[%4];"
                : "=r"(bfr[bg*2][0]), "=r"(bfr[bg*2][1]),
                  "=r"(bfr[bg*2+1][0]), "=r"(bfr[bg*2+1][1])
                : "r"(addr));
        }
        #pragma unroll
        for (int mf = 0; mf < 2; mf++)
            #pragma unroll
            for (int nf = 0; nf < 8; nf++)
                asm volatile(
                    "mma.sync.aligned.m16n8k16.row.col.f32.f16.f16.f32 "
                    "{%0,%1,%2,%3},{%4,%5,%6,%7},{%8,%9},{%0,%1,%2,%3};"
                    : "+f"(acc[mf][nf][0]), "+f"(acc[mf][nf][1]),
                      "+f"(acc[mf][nf][2]), "+f"(acc[mf][nf][3])
                    : "r"(afr[mf][0]), "r"(afr[mf][1]), "r"(afr[mf][2]), "r"(afr[mf][3]),
                      "r"(bfr[nf][0]), "r"(bfr[nf][1]));

        if (c + 1 < NCHUNK) {
            int nb = (c + 1) & 1;
            #pragma unroll
            for (int j = 0; j < 4; j++) As[nb][am][ak+j] = areg[j];
            *reinterpret_cast<uint4*>(&Bs[nb][brow][bcol]) = breg;
        }
        __syncthreads();
    }

    // ---- epilogue: BN + PACT quantization, scattered f32 stores ----
    float aval   = alpha_p[0];
    float back   = __fdiv_rn(aval, 15.0f);     // matches reference's (a/n)
    #pragma unroll
    for (int mf = 0; mf < 2; mf++) {
        #pragma unroll
        for (int jh = 0; jh < 2; jh++) {
            int rm  = m0 + wm*32 + mf*16 + (lane >> 2) + jh*8;
            int b2  = rm / HWHW;
            int hw2 = rm - b2*HWHW;
            float* obase = out + b2*CHAN*HWHW + hw2;
            #pragma unroll
            for (int nf = 0; nf < 8; nf++) {
                #pragma unroll
                for (int jl = 0; jl < 2; jl++) {
                    int j  = jh*2 + jl;
                    int oc = wn*64 + nf*8 + ((lane & 3) << 1) + jl;
                    float y = fmaf(acc[mf][nf][j], s_scale[oc], s_bias[oc]);
                    y = fminf(fmaxf(y, 0.0f), aval);
                    float q = rintf(__fdiv_rn(y * 15.0f, aval)) * back;
                    obase[oc * HWHW] = q;
                }
            }
        }
    }
}

// ---------------- launch ----------------------------------------------------
extern "C" void kernel_launch(void* const* d_in, const int* in_sizes, int n_in,
                              void* d_out, int out_size) {
    const float* x     = (const float*)d_in[0];
    const float* w     = (const float*)d_in[1];
    const float* gamma = (const float*)d_in[2];
    const float* beta  = (const float*)d_in[3];
    const float* mean  = (const float*)d_in[4];
    const float* var   = (const float*)d_in[5];
    const float* alpha = (const float*)d_in[6];
    float* out = (float*)d_out;

    k_reduce1<<<256, 256>>>(w);
    k_reduce2<<<1, 256>>>();
    k_prep_w<<<KDIM, 256>>>(w);            // 2304*256 == 589824 exactly
    k_prep_bn<<<1, CHAN>>>(gamma, beta, mean, var);
    k_convert<<<NX/4/256, 256>>>(x);       // 25088 blocks, exact cover
    k_conv<<<MDIM/BM, 512>>>(alpha, out);  // 784 CTAs
}

// round 3
// speedup vs baseline: 1.2213x; 1.2213x over previous
#include <cuda_runtime.h>
#include <cuda_fp16.h>
#include <math.h>
#include <stdint.h>

// Problem constants
#define BATCH   32
#define CHAN    256
#define HH      56
#define WW      56
#define HWHW    3136
#define NWEIGHT (CHAN*CHAN*9)
#define KDIM    2304
#define MDIM    (BATCH*HWHW)            // 100352

// Padded NHWC activation layout
#define PADW    58
#define XPLANE  (PADW*PADW*CHAN)        // 861184
#define NXPAD   (BATCH*XPLANE)          // 27557888 halves per pass

// GEMM tiling
#define BM 128
#define BN 256
#define BK 32
#define NCHUNK 144                      // 2 passes * 9 taps * 8 ci-chunks
#define STAGES 4
#define ASTRIDE 40                      // 32 + 8 pad (80B rows, LDSM conflict-free)
#define BSTRIDE 264                     // 256 + 8 pad (528B rows, conflict-free)

// ---------------- device scratch (static: no allocations allowed) ----------
__device__ __half g_xpad[2*NXPAD];          // padded NHWC hi/lo split (~110 MB)
__device__ __half g_wmat[9*CHAN*CHAN];      // weights*15 as [tap][ci][oc]
__device__ float  g_scale[CHAN];
__device__ float  g_bias[CHAN];
__device__ float  g_part[256];
__device__ float  g_T;

__device__ __forceinline__ uint32_t smem_u32(const void* p) {
    return (uint32_t)__cvta_generic_to_shared(p);
}

// ---------------- kernel 1: partial max |tanh(w)| ---------------------------
__global__ void k_reduce1(const float* __restrict__ w) {
    __shared__ float s[256];
    float m = 0.0f;
    for (int i = blockIdx.x*256 + threadIdx.x; i < NWEIGHT; i += 256*256) {
        float t = (float)tanh((double)w[i]);
        m = fmaxf(m, fabsf(t));
    }
    s[threadIdx.x] = m;
    __syncthreads();
    for (int o = 128; o > 0; o >>= 1) {
        if (threadIdx.x < o) s[threadIdx.x] = fmaxf(s[threadIdx.x], s[threadIdx.x+o]);
        __syncthreads();
    }
    if (threadIdx.x == 0) g_part[blockIdx.x] = s[0];
}

__global__ void k_reduce2() {
    __shared__ float s[256];
    s[threadIdx.x] = g_part[threadIdx.x];
    __syncthreads();
    for (int o = 128; o > 0; o >>= 1) {
        if (threadIdx.x < o) s[threadIdx.x] = fmaxf(s[threadIdx.x], s[threadIdx.x+o]);
        __syncthreads();
    }
    if (threadIdx.x == 0) g_T = s[0];
}

// ---------------- kernel 2: quantize weights -> m = 15*wq (fp16), [tap][ci][oc]
__global__ void k_prep_w(const float* __restrict__ w) {
    int e = blockIdx.x*256 + threadIdx.x;      // grid KDIM*256 == NWEIGHT exactly
    float T = g_T;
    float t  = (float)tanh((double)w[e]);
    float tq = __fdiv_rn(t, 2.0f*T) + 0.5f;
    float r  = rintf(tq * 15.0f);              // half-even, matches jnp.round
    int oc = e / KDIM;
    int rr = e - oc*KDIM;
    int ci = rr / 9;
    int tap = rr - ci*9;
    g_wmat[(tap*CHAN + ci)*CHAN + oc] = __float2half(2.0f*r - 15.0f);
}

// ---------------- kernel 3: BN fold ----------------------------------------
__global__ void k_prep_bn(const float* __restrict__ gamma, const float* __restrict__ beta,
                          const float* __restrict__ mean,  const float* __restrict__ var) {
    int oc = threadIdx.x;
    float inv = __fdiv_rn(gamma[oc], __fsqrt_rn(var[oc] + 1e-5f));
    g_scale[oc] = __fdiv_rn(inv, 15.0f);
    g_bias[oc]  = fmaf(-mean[oc], inv, beta[oc]);
}

// ---------------- kernel 4: NCHW fp32 -> padded NHWC fp16 hi/lo (transpose) -
__global__ __launch_bounds__(128)
void k_convert(const float* __restrict__ x) {
    __shared__ __half sh[2][56][136];          // [hi/lo][w][ci] 30.5 KB
    int bid = blockIdx.x;                      // 0 .. 32*56*2-1
    int cihalf = bid & 1;
    int bh = bid >> 1;
    int h = bh % HH;
    int b = bh / HH;
    int t = threadIdx.x;

    const float* xp = x + ((size_t)(b*CHAN + cihalf*128)*HH + h)*WW;
    #pragma unroll
    for (int i = 0; i < 14; i++) {
        int f = i*128 + t;                     // 0..1791 (128 ci x 14 float4)
        int ci = f / 14;
        int c4 = f - ci*14;
        float4 v = *reinterpret_cast<const float4*>(xp + (size_t)ci*HWHW + c4*4);
        int w4 = c4*4;
        float vv[4] = {v.x, v.y, v.z, v.w};
        #pragma unroll
        for (int j = 0; j < 4; j++) {
            __half hh = __float2half(vv[j]);
            sh[0][w4+j][ci] = hh;
            sh[1][w4+j][ci] = __float2half(vv[j] - __half2float(hh));
        }
    }
    __syncthreads();
    int obase = b*XPLANE + ((h+1)*PADW + 1)*CHAN + cihalf*128;
    #pragma unroll
    for (int i = 0; i < 7; i++) {
        int u = i*128 + t;                     // 0..895 (56 w x 16 units)
        int w = u >> 4;
        int c16 = (u & 15)*8;
        uint4 dhi = *reinterpret_cast<const uint4*>(&sh[0][w][c16]);
        uint4 dlo = *reinterpret_cast<const uint4*>(&sh[1][w][c16]);
        int o = obase + w*CHAN + c16;
        *reinterpret_cast<uint4*>(&g_xpad[o])         = dhi;
        *reinterpret_cast<uint4*>(&g_xpad[NXPAD + o]) = dlo;
    }
}

// ---------------- main conv: implicit GEMM, cp.async pipeline + mma.sync ----
struct Stage {
    __half A[BM*ASTRIDE];                      // 10240 B
    __half B[BK*BSTRIDE];                      // 16896 B
};

__device__ __forceinline__ void issue_chunk(int c, Stage* st, const __half* abase, int tid) {
    int pass = (c >= 72) ? 1 : 0;
    int cc   = c - pass*72;
    int tap  = cc >> 3;
    int cic  = cc & 7;
    int kh = tap / 3, kw = tap - kh*3;
    // A: one 16B unit per thread (128 pixels x 32 halves)
    const __half* asrc = abase + pass*NXPAD + (kh*PADW + kw)*CHAN + cic*32;
    uint32_t adst = smem_u32(&st->A[(tid>>2)*ASTRIDE + (tid&3)*8]);
    asm volatile("cp.async.cg.shared.global [%0], [%1], 16;\n" :: "r"(adst), "l"(asrc));
    // B: two 16B units per thread (32 rows x 32 units)
    int u = tid;
    #pragma unroll
    for (int r = 0; r < 2; r++, u += 512) {
        int row = u >> 5;
        int cu  = (u & 31)*8;
        const __half* bsrc = g_wmat + ((tap*CHAN + cic*32 + row)*CHAN + cu);
        uint32_t bdst = smem_u32(&st->B[row*BSTRIDE + cu]);
        asm volatile("cp.async.cg.shared.global [%0], [%1], 16;\n" :: "r"(bdst), "l"(bsrc));
    }
}

__global__ __launch_bounds__(512, 1)
void k_conv(const float* __restrict__ alpha_p, float* __restrict__ out) {
    extern __shared__ char dynsmem[];
    Stage* st      = reinterpret_cast<Stage*>(dynsmem);
    float* s_scale = reinterpret_cast<float*>(dynsmem + STAGES*sizeof(Stage));
    float* s_bias  = s_scale + CHAN;

    int tid  = threadIdx.x;
    int warp = tid >> 5, lane = tid & 31;
    int wm = warp >> 2, wn = warp & 3;         // 4x4 warp grid; warp tile 32x64

    if (tid < CHAN) { s_scale[tid] = g_scale[tid]; s_bias[tid] = g_bias[tid]; }

    int m0 = blockIdx.x * BM;
    // per-thread A pixel base
    int pix = tid >> 2;
    int gm  = m0 + pix;
    int b   = gm / HWHW;  int rem = gm - b*HWHW;
    int h   = rem / WW;   int w   = rem - h*WW;
    const __half* abase = g_xpad + b*XPLANE + (h*PADW + w)*CHAN + (tid & 3)*8;

    float acc[2][8][4];
    #pragma unroll
    for (int mf = 0; mf < 2; mf++)
        #pragma unroll
        for (int nf = 0; nf < 8; nf++)
            #pragma unroll
            for (int j = 0; j < 4; j++) acc[mf][nf][j] = 0.0f;

    // prologue: fill STAGES-1 stages
    #pragma unroll
    for (int s = 0; s < STAGES-1; s++) {
        issue_chunk(s, &st[s], abase, tid);
        asm volatile("cp.async.commit_group;\n");
    }

    for (int c = 0; c < NCHUNK; c++) {
        asm volatile("cp.async.wait_group %0;\n" :: "n"(STAGES-2));
        __syncthreads();
        int cn = c + STAGES - 1;
        if (cn < NCHUNK) issue_chunk(cn, &st[cn & (STAGES-1)], abase, tid);
        asm volatile("cp.async.commit_group;\n");

        const __half* Ab = st[c & (STAGES-1)].A;
        const __half* Bb = st[c & (STAGES-1)].B;
        #pragma unroll
        for (int kk = 0; kk < 2; kk++) {
            uint32_t afr[2][4];
            uint32_t bfr[8][2];
            #pragma unroll
            for (int mf = 0; mf < 2; mf++) {
                int row = wm*32 + mf*16 + (lane & 15);
                int col = kk*16 + ((lane >> 4) << 3);
                uint32_t addr = smem_u32(&Ab[row*ASTRIDE + col]);
                asm volatile("ldmatrix.sync.aligned.m8n8.x4.shared.b16 {%0,%1,%2,%3},[%4];"
                    : "=r"(afr[mf][0]), "=r"(afr[mf][1]), "=r"(afr[mf][2]), "=r"(afr[mf][3])
                    : "r"(addr));
            }
            #pragma unroll
            for (int bg = 0; bg < 4; bg++) {
                int row = kk*16 + (lane & 15);
                int col = wn*64 + bg*16 + ((lane >> 4) << 3);
                uint32_t addr = smem_u32(&Bb[row*BSTRIDE + col]);
                asm volatile("ldmatrix.sync.aligned.m8n8.x4.trans.shared.b16 {%0,%1,%2,%3},[%4];"
                    : "=r"(bfr[bg*2][0]), "=r"(bfr[bg*2][1]),
                      "=r"(bfr[bg*2+1][0]), "=r"(bfr[bg*2+1][1])
                    : "r"(addr));
            }
            #pragma unroll
            for (int mf = 0; mf < 2; mf++)
                #pragma unroll
                for (int nf = 0; nf < 8; nf++)
                    asm volatile(
                        "mma.sync.aligned.m16n8k16.row.col.f32.f16.f16.f32 "
                        "{%0,%1,%2,%3},{%4,%5,%6,%7},{%8,%9},{%0,%1,%2,%3};"
                        : "+f"(acc[mf][nf][0]), "+f"(acc[mf][nf][1]),
                          "+f"(acc[mf][nf][2]), "+f"(acc[mf][nf][3])
                        : "r"(afr[mf][0]), "r"(afr[mf][1]), "r"(afr[mf][2]), "r"(afr[mf][3]),
                          "r"(bfr[nf][0]), "r"(bfr[nf][1]));
        }
    }

    // ---- epilogue: BN + PACT quantization ----
    float aval = alpha_p[0];
    float back = __fdiv_rn(aval, 15.0f);
    #pragma unroll
    for (int mf = 0; mf < 2; mf++) {
        #pragma unroll
        for (int jh = 0; jh < 2; jh++) {
            int rm  = m0 + wm*32 + mf*16 + (lane >> 2) + jh*8;
            int b2  = rm / HWHW;
            int hw2 = rm - b2*HWHW;
            float* obase = out + b2*CHAN*HWHW + hw2;
            #pragma unroll
            for (int nf = 0; nf < 8; nf++) {
                #pragma unroll
                for (int jl = 0; jl < 2; jl++) {
                    int j  = jh*2 + jl;
                    int oc = wn*64 + nf*8 + ((lane & 3) << 1) + jl;
                    float y = fmaf(acc[mf][nf][j], s_scale[oc], s_bias[oc]);
                    y = fminf(fmaxf(y, 0.0f), aval);
                    float q = rintf(__fdiv_rn(y * 15.0f, aval)) * back;
                    obase[oc * HWHW] = q;
                }
            }
        }
    }
}

// ---------------- launch ----------------------------------------------------
extern "C" void kernel_launch(void* const* d_in, const int* in_sizes, int n_in,
                              void* d_out, int out_size) {
    const float* x     = (const float*)d_in[0];
    const float* w     = (const float*)d_in[1];
    const float* gamma = (const float*)d_in[2];
    const float* beta  = (const float*)d_in[3];
    const float* mean  = (const float*)d_in[4];
    const float* var   = (const float*)d_in[5];
    const float* alpha = (const float*)d_in[6];
    float* out = (float*)d_out;

    static int smem_set = 0;
    int smem_bytes = (int)(STAGES*sizeof(Stage)) + 2*CHAN*(int)sizeof(float);
    if (!smem_set) {
        cudaFuncSetAttribute(k_conv, cudaFuncAttributeMaxDynamicSharedMemorySize, smem_bytes);
        smem_set = 1;
    }

    k_reduce1<<<256, 256>>>(w);
    k_reduce2<<<1, 256>>>();
    k_prep_w<<<KDIM, 256>>>(w);
    k_prep_bn<<<1, CHAN>>>(gamma, beta, mean, var);
    k_convert<<<BATCH*HH*2, 128>>>(x);
    k_conv<<<MDIM/BM, 512, smem_bytes>>>(alpha, out);
}